// round 3
// baseline (speedup 1.0000x reference)
#include <cuda_runtime.h>
#include <math.h>

#define NN     20000
#define FIN    128
#define HC     256
#define NHEADS 8
#define HID    32
#define NE     320000
#define ET     (NE + NN)
#define NG     64
#define NCLS   10

// ---------------- scratch (static device globals; no allocation) ----------------
__device__ __align__(16) float g_h[(size_t)NN * HC];     // current layer's h = in @ W
__device__ __align__(16) float g_buf[(size_t)NN * HC];   // layer output / next input
__device__ float g_aL[NN * NHEADS];        // att_l . h_j  per node/head
__device__ float g_aR[NN * NHEADS];        // att_r . h_i  per node/head
__device__ int   g_deg[NN];
__device__ int   g_off[NN + 1];
__device__ int   g_cur[NN];
__device__ int   g_csr[ET];
__device__ __align__(16) float g_pool[NG * HC];
__device__ float g_cnt[NG];
__device__ int   g_is64;                   // 1 if index tensors are int64, else int32

// ---------------- dtype probe + zero scratch ----------------
// Interpret edge buffer as int32 words. If the data is int64 (values < 2^31),
// every odd word (high half) is 0. For int32 data the odd words are real
// src-indices (random 0..N) -> essentially never all zero.
__global__ void init_kernel(const int* __restrict__ ei_words) {
    int i = blockIdx.x * blockDim.x + threadIdx.x;
    if (i < NN) g_deg[i] = 0;
    if (i < NG * HC) g_pool[i] = 0.f;
    if (i < NG) g_cnt[i] = 0.f;
    if (blockIdx.x == 0 && threadIdx.x < 64) {
        int w = ei_words[2 * threadIdx.x + 1];          // first 512 bytes: safe either way
        unsigned nz = __ballot_sync(0xffffffffu, w != 0);
        if (threadIdx.x == 0) g_is64 = (nz == 0u) ? 1 : 0;
    }
}

__device__ __forceinline__ int load_idx(const void* p, long long i) {
    return g_is64 ? (int)((const long long*)p)[i] : ((const int*)p)[i];
}

// ---------------- CSR build ----------------
__global__ void hist_kernel(const void* __restrict__ ei) {
    int e = blockIdx.x * blockDim.x + threadIdx.x;
    if (e >= ET) return;
    int dst = (e < NE) ? load_idx(ei, (long long)NE + e) : (e - NE);
    atomicAdd(&g_deg[dst], 1);
}

__global__ void scan_kernel() {
    __shared__ int s[1024];
    const int CH = 20;                       // 1024*20 = 20480 >= NN
    int t = threadIdx.x;
    int base = t * CH;
    int sum = 0;
#pragma unroll
    for (int c = 0; c < CH; c++) {
        int i = base + c;
        if (i < NN) sum += g_deg[i];
    }
    s[t] = sum;
    __syncthreads();
    for (int o = 1; o < 1024; o <<= 1) {
        int v = (t >= o) ? s[t - o] : 0;
        __syncthreads();
        s[t] += v;
        __syncthreads();
    }
    int pre = s[t] - sum;                    // exclusive prefix for this chunk
#pragma unroll
    for (int c = 0; c < CH; c++) {
        int i = base + c;
        if (i < NN) {
            g_off[i] = pre;
            g_cur[i] = pre;
            pre += g_deg[i];
        }
    }
    if (t == 1023) g_off[NN] = s[1023];
}

__global__ void fill_kernel(const void* __restrict__ ei) {
    int e = blockIdx.x * blockDim.x + threadIdx.x;
    if (e >= ET) return;
    int src, dst;
    if (e < NE) { src = load_idx(ei, e); dst = load_idx(ei, (long long)NE + e); }
    else        { src = dst = e - NE; }
    int pos = atomicAdd(&g_cur[dst], 1);
    g_csr[pos] = src;
}

// ---------------- GEMM: C[M,256] = A[M,K] @ B[K,256] -> g_h ----------------
// srcSel: 0 -> external A, 1 -> g_buf
__global__ void gemm_kernel(const float* __restrict__ Aext, const float* __restrict__ B,
                            int M, int K, int srcSel) {
    __shared__ float As[16][68];   // padded: conflict-free transposed store
    __shared__ float Bs[16][64];
    const float* A = srcSel ? (const float*)g_buf : Aext;
    float* C = g_h;
    int tid = threadIdx.x;
    int tx = tid & 15, ty = tid >> 4;
    int m0 = blockIdx.y * 64, n0 = blockIdx.x * 64;
    float acc[4][4] = {};
    for (int k0 = 0; k0 < K; k0 += 16) {
#pragma unroll
        for (int i = tid; i < 1024; i += 256) {
            int m = i >> 4, k = i & 15;
            int gm = m0 + m;
            As[k][m] = (gm < M) ? A[(size_t)gm * K + k0 + k] : 0.f;
        }
#pragma unroll
        for (int i = tid; i < 1024; i += 256) {
            int k = i >> 6, n = i & 63;
            Bs[k][n] = B[(size_t)(k0 + k) * HC + n0 + n];
        }
        __syncthreads();
#pragma unroll
        for (int k = 0; k < 16; k++) {
            float a[4], b[4];
#pragma unroll
            for (int i = 0; i < 4; i++) a[i] = As[k][ty * 4 + i];
#pragma unroll
            for (int j = 0; j < 4; j++) b[j] = Bs[k][tx * 4 + j];
#pragma unroll
            for (int i = 0; i < 4; i++)
#pragma unroll
                for (int j = 0; j < 4; j++) acc[i][j] += a[i] * b[j];
        }
        __syncthreads();
    }
#pragma unroll
    for (int i = 0; i < 4; i++) {
        int gm = m0 + ty * 4 + i;
        if (gm < M) {
            float4 v = make_float4(acc[i][0], acc[i][1], acc[i][2], acc[i][3]);
            *(float4*)(C + (size_t)gm * HC + n0 + tx * 4) = v;
        }
    }
}

// ---------------- per-node attention dot terms (reads g_h) ----------------
__global__ void alr_kernel(const float* __restrict__ attl,
                           const float* __restrict__ attr) {
    int w = (blockIdx.x * blockDim.x + threadIdx.x) >> 5;
    if (w >= NN) return;
    int lane = threadIdx.x & 31;
    const float4* hp = (const float4*)(g_h + (size_t)w * HC + lane * 8);
    float4 h0 = hp[0], h1 = hp[1];
    const float4* lp = (const float4*)(attl + lane * 8);
    const float4* rp = (const float4*)(attr + lane * 8);
    float4 l0 = lp[0], l1 = lp[1], r0 = rp[0], r1 = rp[1];
    float sl = h0.x * l0.x + h0.y * l0.y + h0.z * l0.z + h0.w * l0.w
             + h1.x * l1.x + h1.y * l1.y + h1.z * l1.z + h1.w * l1.w;
    float sr = h0.x * r0.x + h0.y * r0.y + h0.z * r0.z + h0.w * r0.w
             + h1.x * r1.x + h1.y * r1.y + h1.z * r1.z + h1.w * r1.w;
    sl += __shfl_xor_sync(0xffffffffu, sl, 1);
    sl += __shfl_xor_sync(0xffffffffu, sl, 2);
    sr += __shfl_xor_sync(0xffffffffu, sr, 1);
    sr += __shfl_xor_sync(0xffffffffu, sr, 2);
    if ((lane & 3) == 0) {
        g_aL[w * NHEADS + (lane >> 2)] = sl;
        g_aR[w * NHEADS + (lane >> 2)] = sr;
    }
}

// ---------------- fused edge-attention + segment softmax + aggregate ----------------
// One warp per dst node. lane owns channels [8*lane, 8*lane+8).
// Reads g_h, writes g_buf.
__global__ void attn_kernel(const float* __restrict__ bias, int applyElu) {
    int w = (blockIdx.x * blockDim.x + threadIdx.x) >> 5;
    if (w >= NN) return;
    int lane = threadIdx.x & 31;
    int head = lane >> 2;
    const float* h = g_h;
    const float4* hp = (const float4*)(h + (size_t)w * HC + lane * 8);
    float4 xi0 = hp[0], xi1 = hp[1];
    float aRi = g_aR[w * NHEADS + head];
    float m = -INFINITY, d = 0.f;
    float4 a0 = make_float4(0.f, 0.f, 0.f, 0.f);
    float4 a1 = make_float4(0.f, 0.f, 0.f, 0.f);
    int s = g_off[w], e = g_off[w + 1];
    for (int k = s; k < e; k++) {
        int j = g_csr[k];
        const float4* jp = (const float4*)(h + (size_t)j * HC + lane * 8);
        float4 xj0 = jp[0], xj1 = jp[1];
        float pd = xi0.x * xj0.x + xi0.y * xj0.y + xi0.z * xj0.z + xi0.w * xj0.w
                 + xi1.x * xj1.x + xi1.y * xj1.y + xi1.z * xj1.z + xi1.w * xj1.w;
        pd += __shfl_xor_sync(0xffffffffu, pd, 1);
        pd += __shfl_xor_sync(0xffffffffu, pd, 2);
        float alpha = (g_aL[j * NHEADS + head] + aRi) * (1.f / (1.f + __expf(-pd)));
        alpha = alpha > 0.f ? alpha : 0.2f * alpha;          // leaky_relu 0.2
        float mn = fmaxf(m, alpha);
        float sc = __expf(m - mn);                            // exp(-inf)=0 on first edge
        float wt = __expf(alpha - mn);
        d = d * sc + wt;
        m = mn;
        a0.x = a0.x * sc + wt * xj0.x;  a0.y = a0.y * sc + wt * xj0.y;
        a0.z = a0.z * sc + wt * xj0.z;  a0.w = a0.w * sc + wt * xj0.w;
        a1.x = a1.x * sc + wt * xj1.x;  a1.y = a1.y * sc + wt * xj1.y;
        a1.z = a1.z * sc + wt * xj1.z;  a1.w = a1.w * sc + wt * xj1.w;
    }
    float inv = 1.f / (d + 1e-16f);
    const float4* bp = (const float4*)(bias + lane * 8);
    float4 b0 = bp[0], b1 = bp[1];
    float4 o0, o1;
    o0.x = a0.x * inv + b0.x;  o0.y = a0.y * inv + b0.y;
    o0.z = a0.z * inv + b0.z;  o0.w = a0.w * inv + b0.w;
    o1.x = a1.x * inv + b1.x;  o1.y = a1.y * inv + b1.y;
    o1.z = a1.z * inv + b1.z;  o1.w = a1.w * inv + b1.w;
    if (applyElu) {
        o0.x = o0.x > 0.f ? o0.x : (expf(o0.x) - 1.f);
        o0.y = o0.y > 0.f ? o0.y : (expf(o0.y) - 1.f);
        o0.z = o0.z > 0.f ? o0.z : (expf(o0.z) - 1.f);
        o0.w = o0.w > 0.f ? o0.w : (expf(o0.w) - 1.f);
        o1.x = o1.x > 0.f ? o1.x : (expf(o1.x) - 1.f);
        o1.y = o1.y > 0.f ? o1.y : (expf(o1.y) - 1.f);
        o1.z = o1.z > 0.f ? o1.z : (expf(o1.z) - 1.f);
        o1.w = o1.w > 0.f ? o1.w : (expf(o1.w) - 1.f);
    }
    float4* op = (float4*)(g_buf + (size_t)w * HC + lane * 8);
    op[0] = o0;
    op[1] = o1;
}

// ---------------- mean pool + classifier ----------------
__global__ void pool_kernel(const void* __restrict__ batch) {
    int idx = blockIdx.x * blockDim.x + threadIdx.x;
    if (idx >= NN * 64) return;
    int node = idx >> 6, q = idx & 63;
    int g = load_idx(batch, node);
    float4 v = ((const float4*)(g_buf + (size_t)node * HC))[q];
    float* p = &g_pool[g * HC + q * 4];
    atomicAdd(p + 0, v.x);
    atomicAdd(p + 1, v.y);
    atomicAdd(p + 2, v.z);
    atomicAdd(p + 3, v.w);
    if (q == 0) atomicAdd(&g_cnt[g], 1.f);
}

__global__ void final_kernel(const float* __restrict__ linW, const float* __restrict__ linb,
                             float* __restrict__ out) {
    int g = blockIdx.x;
    int c = threadIdx.x;
    if (c >= NCLS) return;
    float inv = 1.f / fmaxf(g_cnt[g], 1.f);
    float s = linb[c];
    for (int k = 0; k < HC; k++)
        s += g_pool[g * HC + k] * inv * linW[k * NCLS + c];
    out[g * NCLS + c] = s;
}

// ---------------- launch ----------------
extern "C" void kernel_launch(void* const* d_in, const int* in_sizes, int n_in,
                              void* d_out, int out_size) {
    const float* x     = (const float*)d_in[0];
    const void*  ei    = d_in[1];
    const void*  batch = d_in[2];
    const float* W1    = (const float*)d_in[3];
    const float* attl1 = (const float*)d_in[4];
    const float* attr1 = (const float*)d_in[5];
    const float* b1    = (const float*)d_in[6];
    const float* W2    = (const float*)d_in[7];
    const float* attl2 = (const float*)d_in[8];
    const float* attr2 = (const float*)d_in[9];
    const float* b2    = (const float*)d_in[10];
    const float* linW  = (const float*)d_in[11];
    const float* linb  = (const float*)d_in[12];
    float*       out   = (float*)d_out;

    // Probe index dtype, zero scratch, build CSR (includes self loops).
    init_kernel<<<(NN + 255) / 256, 256>>>((const int*)ei);
    hist_kernel<<<(ET + 255) / 256, 256>>>(ei);
    scan_kernel<<<1, 1024>>>();
    fill_kernel<<<(ET + 255) / 256, 256>>>(ei);

    dim3 gg(HC / 64, (NN + 63) / 64);
    const int ATTN_BLOCKS = (NN * 32 + 255) / 256;

    // Layer 1
    gemm_kernel<<<gg, 256>>>(x, W1, NN, FIN, 0);
    alr_kernel<<<ATTN_BLOCKS, 256>>>(attl1, attr1);
    attn_kernel<<<ATTN_BLOCKS, 256>>>(b1, 1);

    // Layer 2 (reads g_buf)
    gemm_kernel<<<gg, 256>>>(nullptr, W2, NN, HC, 1);
    alr_kernel<<<ATTN_BLOCKS, 256>>>(attl2, attr2);
    attn_kernel<<<ATTN_BLOCKS, 256>>>(b2, 0);

    // Mean pool + classifier
    pool_kernel<<<(NN * 64 + 255) / 256, 256>>>(batch);
    final_kernel<<<NG, 32>>>(linW, linb, out);
}